// round 10
// baseline (speedup 1.0000x reference)
#include <cuda_runtime.h>
#include <cuda_bf16.h>
#include <cstdint>

// ---------------- problem constants ----------------
#define NIMG 32
#define CH   256
#define HH   36
#define WW   36
#define HWSZ 1296
#define MTOT (NIMG*HWSZ)   // 41472
#define KTOT (CH*9)        // 2304
#define NK2  (KTOT/2)      // 1152
#define NROI 512
#define FCK  4096
#define EPS_BN 1e-5f
#define CHW  (CH*HWSZ)

// ---------------- scratch ----------------
__device__ float    g_bufA[MTOT*CH];        // conv output, NHWC fp32
__device__ uint32_t g_aH[8*MTOT*16];        // activations [cc][m][16w] bf16x2 hi
__device__ uint32_t g_aL[8*MTOT*16];        // same, lo residual
__device__ uint32_t g_wb[72*2*256*16];      // weights [ch][half][n][16w] bf16x2
__device__ float g_ft [MTOT*CH];            // NHWC feat (pool phase)
__device__ float g_Ux [MTOT*CH];
__device__ float g_Uy [MTOT*CH];
__device__ float g_T  [MTOT*CH];
__device__ float g_rf [NROI*FCK];
__device__ float g_fc [NROI*CH];
__device__ float g_sum[CH], g_sq[CH];
__device__ float g_fsum[CH], g_fsq[CH];

// ---------------- helpers ----------------
__device__ __forceinline__ uint32_t smem_u32(const void* p) {
    uint32_t a;
    asm("{ .reg .u64 t; cvta.to.shared.u64 t, %1; cvt.u32.u64 %0, t; }" : "=r"(a) : "l"(p));
    return a;
}
__device__ __forceinline__ void bfsplit(float v, uint16_t& hi, uint16_t& lo) {
    __nv_bfloat16 h = __float2bfloat16(v);
    __nv_bfloat16 l = __float2bfloat16(v - __bfloat162float(h));
    hi = __bfloat16_as_ushort(h);
    lo = __bfloat16_as_ushort(l);
}
__device__ __forceinline__ void mma16(float d[4], const uint32_t a[4], const uint32_t b[2]) {
    asm volatile("mma.sync.aligned.m16n8k16.row.col.f32.bf16.bf16.f32 "
        "{%0,%1,%2,%3},{%4,%5,%6,%7},{%8,%9},{%0,%1,%2,%3};"
        : "+f"(d[0]), "+f"(d[1]), "+f"(d[2]), "+f"(d[3])
        : "r"(a[0]), "r"(a[1]), "r"(a[2]), "r"(a[3]), "r"(b[0]), "r"(b[1]));
}
#define LDM4(r, addr) \
    asm volatile("ldmatrix.sync.aligned.m8n8.x4.shared.b16 {%0,%1,%2,%3}, [%4];" \
        : "=r"((r)[0]), "=r"((r)[1]), "=r"((r)[2]), "=r"((r)[3]) : "r"(addr))
__device__ __forceinline__ void cp16s(uint32_t dst, const void* src, uint32_t sz) {
    asm volatile("cp.async.cg.shared.global [%0], [%1], 16, %2;" :: "r"(dst), "l"(src), "r"(sz));
}
__device__ __forceinline__ void cp16(uint32_t dst, const void* src) {
    asm volatile("cp.async.cg.shared.global [%0], [%1], 16;" :: "r"(dst), "l"(src));
}
#define CP_COMMIT() asm volatile("cp.async.commit_group;" ::: "memory")
#define CP_WAIT1()  asm volatile("cp.async.wait_group 1;"  ::: "memory")

// ---------------- weight prep: [ch][half][n][16w] + conv-stat zeroing ----------------
__global__ void k_wprep(const float* __restrict__ W) {
    int idx = blockIdx.x * 256 + threadIdx.x;   // idx = k2*256 + n
    if (blockIdx.x == 0) {
        g_sum[threadIdx.x] = 0.f;
        g_sq [threadIdx.x] = 0.f;
    }
    int n   = idx & 255;
    int k2  = idx >> 8;
    int ci2 = k2 & 127;
    int tap = k2 >> 7;
    int cc  = ci2 >> 4;
    int jw  = ci2 & 15;
    int ch  = tap * 8 + cc;
    float v0 = __ldg(&W[(size_t)n * KTOT + (2 * ci2)     * 9 + tap]);
    float v1 = __ldg(&W[(size_t)n * KTOT + (2 * ci2 + 1) * 9 + tap]);
    uint16_t h0, l0, h1, l1;
    bfsplit(v0, h0, l0);
    bfsplit(v1, h1, l1);
    g_wb[((size_t)(ch * 2)     * 256 + n) * 16 + jw] = ((uint32_t)h1 << 16) | h0;
    g_wb[((size_t)(ch * 2 + 1) * 256 + n) * 16 + jw] = ((uint32_t)l1 << 16) | l0;
}

// ---------------- conv1 input prep: NCHW -> packed [cc][m][16w] via smem transpose ----------------
__global__ void k_cvtA_t(const float* __restrict__ feat) {
    __shared__ float s[32][33];
    const int cc = blockIdx.x;   // 0..7 (32 channels = 16 ci2)
    const int n  = blockIdx.y;   // image
    const int pb = blockIdx.z;   // 0..40
    const int tx = threadIdx.x, ty = threadIdx.y;
    const int tid = ty * 32 + tx;
    const int p0 = pb * 32;
#pragma unroll
    for (int yy = 0; yy < 4; ++yy) {
        int cl = ty + yy * 8;
        int c  = cc * 32 + cl;
        int p  = p0 + tx;
        s[cl][tx] = (p < HWSZ) ? __ldg(&feat[((size_t)n * CH + c) * HWSZ + p]) : 0.f;
    }
    __syncthreads();
    if (tid < 128) {
        const int ml = tid >> 2;        // 0..31
        const int q  = tid & 3;         // uint4 group
        const int p  = p0 + ml;
        if (p < HWSZ) {
            const int m = n * HWSZ + p;
            uint32_t hw[4], lw[4];
#pragma unroll
            for (int w = 0; w < 4; ++w) {
                const int cl = 2 * (q * 4 + w);
                uint16_t h0, l0, h1, l1;
                bfsplit(s[cl][ml],     h0, l0);
                bfsplit(s[cl + 1][ml], h1, l1);
                hw[w] = ((uint32_t)h1 << 16) | h0;
                lw[w] = ((uint32_t)l1 << 16) | l0;
            }
            *(uint4*)&g_aH[((size_t)cc * MTOT + m) * 16 + q * 4] = *(uint4*)hw;
            *(uint4*)&g_aL[((size_t)cc * MTOT + m) * 16 + q * 4] = *(uint4*)lw;
        }
    }
}

// ===== 3-stage pipelined bf16x3 m16n8k16 conv, ldmatrix + swizzled tiles, 2 CTAs/SM =====
// CTA 128(M)x128(N), 128 threads (4 warps, warp tile 64x64); K = 72 chunks of 32.
// Stage: Ahi[128][64B] Alo Bhi[128][64B] Blo = 32768 B; rows 64B with 16B-group swizzle
// grp_stored = grp_logical ^ ((row>>1)&3).  3 stages = 98304 B.
#define NCHNK 72
#define STG_B 32768

__global__ void __launch_bounds__(128, 2) k_conv_m(const float* __restrict__ bias)
{
    extern __shared__ uint32_t dynu[];
    __shared__ float sRed1[128], sRed2[128];
    const uint32_t sb = smem_u32(dynu);

    const int tid  = threadIdx.x;
    const int lane = tid & 31, wid = tid >> 5;
    const int mt   = blockIdx.x * 128, nt = blockIdx.y * 128;
    const int wm   = (wid >> 1) * 64, wn = (wid & 1) * 64;
    const int g    = lane >> 2, c0 = lane & 3;

    sRed1[tid] = 0.f; sRed2[tid] = 0.f;

    // A-fill mapping: thread owns m-row tid
    const int mA    = mt + tid;
    const int nimgA = mA / HWSZ;
    const int remA  = mA - nimgA * HWSZ;
    const int hA    = remA / WW;
    const int wA    = remA - hA * WW;
    const int aimg  = nimgA * HWSZ;
    const uint32_t fillSwz = ((uint32_t)(tid >> 1) & 3);    // write-side swizzle sel

    // ldmatrix lane constants
    const int tq = lane >> 3, tr = lane & 7;
    const int mrow_base = wm + (tq & 1) * 8 + tr;   // A rows
    const int grpA      = tq >> 1;
    const int selA      = (mrow_base >> 1) & 3;
    const int nrow_base = wn + ((tq >> 1) & 1) * 8 + tr;  // B rows
    const int grpB      = tq & 1;
    const int selB      = (nrow_base >> 1) & 3;

    float acc[4][8][4];
#pragma unroll
    for (int a = 0; a < 4; ++a)
#pragma unroll
        for (int b = 0; b < 8; ++b)
#pragma unroll
            for (int c = 0; c < 4; ++c) acc[a][b][c] = 0.f;

    auto fillA = [&](int st, int ch, int half) {
        const int tap = ch >> 3, cc = ch & 7;
        const int hh = hA + tap / 3 - 1, ww = wA + tap % 3 - 1;
        const bool valid = ((unsigned)hh < HH) && ((unsigned)ww < WW);
        const uint32_t sz = valid ? 16u : 0u;
        const uint32_t* p = (half ? g_aL : g_aH)
                          + ((size_t)cc * MTOT + (valid ? (aimg + hh * WW + ww) : 0)) * 16;
        const uint32_t d = sb + st * STG_B + half * 8192 + tid * 64;
#pragma unroll
        for (int j = 0; j < 4; ++j)
            cp16s(d + ((j ^ fillSwz) << 4), p + j * 4, sz);
    };
    auto fillB = [&](int st, int ch, int half) {
        const uint32_t* p = g_wb + ((size_t)(ch * 2 + half) * 256 + nt + tid) * 16;
        const uint32_t d = sb + st * STG_B + 16384 + half * 8192 + tid * 64;
#pragma unroll
        for (int j = 0; j < 4; ++j)
            cp16(d + ((j ^ fillSwz) << 4), p + j * 4);
    };

    // prologue: stages 0 and 1 (chunks 0 and 1)
    fillA(0, 0, 0); fillA(0, 0, 1); fillB(0, 0, 0); fillB(0, 0, 1); CP_COMMIT();
    fillA(1, 1, 0); fillA(1, 1, 1); fillB(1, 1, 0); fillB(1, 1, 1); CP_COMMIT();

    int stc = 0, stf = 2;
    for (int ch = 0; ch < NCHNK; ++ch) {
        CP_WAIT1();
        __syncthreads();
        const bool pf = (ch + 2) < NCHNK;
        const uint32_t stb = sb + stc * STG_B;
#pragma unroll
        for (int kk = 0; kk < 2; ++kk) {
            if (pf) {   // interleave chunk ch+2's fill under the tensor pipe
                if (kk == 0) { fillA(stf, ch + 2, 0); fillA(stf, ch + 2, 1); }
                else         { fillB(stf, ch + 2, 0); fillB(stf, ch + 2, 1); }
            }
            uint32_t ah[4][4], al[4][4], bh[8][2], bl[8][2];
            const uint32_t aoffH = stb + mrow_base * 64 + (((kk * 2 + grpA) ^ selA) << 4);
            const uint32_t boffH = stb + 16384 + nrow_base * 64 + (((kk * 2 + grpB) ^ selB) << 4);
#pragma unroll
            for (int mf = 0; mf < 4; ++mf) {
                LDM4(ah[mf], aoffH + mf * 1024);
                LDM4(al[mf], aoffH + mf * 1024 + 8192);
            }
#pragma unroll
            for (int np = 0; np < 4; ++np) {
                uint32_t r[4];
                LDM4(r, boffH + np * 1024);
                bh[2*np][0] = r[0]; bh[2*np][1] = r[1];
                bh[2*np+1][0] = r[2]; bh[2*np+1][1] = r[3];
                LDM4(r, boffH + np * 1024 + 8192);
                bl[2*np][0] = r[0]; bl[2*np][1] = r[1];
                bl[2*np+1][0] = r[2]; bl[2*np+1][1] = r[3];
            }
#pragma unroll
            for (int mf = 0; mf < 4; ++mf)
#pragma unroll
                for (int nf = 0; nf < 8; ++nf)
                    mma16(acc[mf][nf], ah[mf], bh[nf]);
#pragma unroll
            for (int mf = 0; mf < 4; ++mf)
#pragma unroll
                for (int nf = 0; nf < 8; ++nf)
                    mma16(acc[mf][nf], ah[mf], bl[nf]);
#pragma unroll
            for (int mf = 0; mf < 4; ++mf)
#pragma unroll
                for (int nf = 0; nf < 8; ++nf)
                    mma16(acc[mf][nf], al[mf], bh[nf]);
        }
        CP_COMMIT();
        stc = (stc == 2) ? 0 : stc + 1;
        stf = (stf == 2) ? 0 : stf + 1;
    }

    // ---------------- epilogue: bias, NHWC store, fused stats ----------------
    float s1[16], s2[16];
#pragma unroll
    for (int i = 0; i < 16; ++i) { s1[i] = 0.f; s2[i] = 0.f; }

#pragma unroll
    for (int mf = 0; mf < 4; ++mf) {
#pragma unroll
        for (int rr = 0; rr < 2; ++rr) {
            const int m = mt + wm + mf * 16 + g + rr * 8;
            float* orow = g_bufA + (size_t)m * CH;
#pragma unroll
            for (int nf = 0; nf < 8; ++nf) {
                const int c = nt + wn + nf * 8 + c0 * 2;
                const float v0 = acc[mf][nf][rr * 2]     + __ldg(&bias[c]);
                const float v1 = acc[mf][nf][rr * 2 + 1] + __ldg(&bias[c + 1]);
                *(float2*)(orow + c) = make_float2(v0, v1);
                s1[nf * 2]     += v0; s2[nf * 2]     += v0 * v0;
                s1[nf * 2 + 1] += v1; s2[nf * 2 + 1] += v1 * v1;
            }
        }
    }
    __syncthreads();
#pragma unroll
    for (int nf = 0; nf < 8; ++nf) {
        const int cl = wn + nf * 8 + c0 * 2;
        atomicAdd(&sRed1[cl],     s1[nf * 2]);
        atomicAdd(&sRed2[cl],     s2[nf * 2]);
        atomicAdd(&sRed1[cl + 1], s1[nf * 2 + 1]);
        atomicAdd(&sRed2[cl + 1], s2[nf * 2 + 1]);
    }
    __syncthreads();
    atomicAdd(&g_sum[nt + tid], sRed1[tid]);
    atomicAdd(&g_sq [nt + tid], sRed2[tid]);
}

// ---------------- BN + ReLU (NHWC in), packed [cc][m][16w] bf16-pair out ----------------
__global__ void k_bnrelu_split(const float* __restrict__ gm,
                               const float* __restrict__ bt)
{
    __shared__ float ssc[CH], ssh[CH];
    const int tid = threadIdx.x;
    const float invN = 1.0f / (float)MTOT;
    {
        const int c = tid;
        float m = g_sum[c] * invN;
        float v = g_sq[c] * invN - m * m;
        float sc = rsqrtf(v + EPS_BN) * __ldg(&gm[c]);
        ssc[c] = sc;
        ssh[c] = __ldg(&bt[c]) - m * sc;
    }
    __syncthreads();

    const int i   = blockIdx.x * 256 + tid;   // i = m*8 + cc
    const int m   = i >> 3;
    const int cc  = i & 7;
    const float* row = g_bufA + (size_t)m * CH + cc * 32;
    uint32_t hw[16], lw[16];
#pragma unroll
    for (int w = 0; w < 16; ++w) {
        const int c = cc * 32 + 2 * w;
        float2 x = *(const float2*)(row + 2 * w);
        float y0 = fmaxf(fmaf(x.x, ssc[c],     ssh[c]),     0.f);
        float y1 = fmaxf(fmaf(x.y, ssc[c + 1], ssh[c + 1]), 0.f);
        uint16_t h0, l0, h1, l1;
        bfsplit(y0, h0, l0);
        bfsplit(y1, h1, l1);
        hw[w] = ((uint32_t)h1 << 16) | h0;
        lw[w] = ((uint32_t)l1 << 16) | l0;
    }
    uint4* dh = (uint4*)&g_aH[((size_t)cc * MTOT + m) * 16];
    uint4* dl = (uint4*)&g_aL[((size_t)cc * MTOT + m) * 16];
#pragma unroll
    for (int q = 0; q < 4; ++q) {
        dh[q] = *(uint4*)&hw[q * 4];
        dl[q] = *(uint4*)&lw[q * 4];
    }
}

// ---------------- final BN + ReLU: NHWC -> g_ft NHWC (elementwise) ----------------
__global__ void k_bnrelu_final(const float* __restrict__ gm,
                               const float* __restrict__ bt)
{
    const float invN = 1.0f / (float)MTOT;
    int i4 = blockIdx.x * blockDim.x + threadIdx.x;
    int c  = (i4 * 4) & (CH - 1);
    float4 x = ((const float4*)g_bufA)[i4];
    float m0 = g_sum[c] * invN, vv0 = g_sq[c] * invN - m0 * m0;
    float a0 = rsqrtf(vv0 + EPS_BN) * __ldg(&gm[c]);
    float b0 = __ldg(&bt[c]) - m0 * a0;
    float m1 = g_sum[c+1] * invN, vv1 = g_sq[c+1] * invN - m1 * m1;
    float a1 = rsqrtf(vv1 + EPS_BN) * __ldg(&gm[c+1]);
    float b1 = __ldg(&bt[c+1]) - m1 * a1;
    float m2 = g_sum[c+2] * invN, vv2 = g_sq[c+2] * invN - m2 * m2;
    float a2 = rsqrtf(vv2 + EPS_BN) * __ldg(&gm[c+2]);
    float b2 = __ldg(&bt[c+2]) - m2 * a2;
    float m3 = g_sum[c+3] * invN, vv3 = g_sq[c+3] * invN - m3 * m3;
    float a3 = rsqrtf(vv3 + EPS_BN) * __ldg(&gm[c+3]);
    float b3 = __ldg(&bt[c+3]) - m3 * a3;
    x.x = fmaxf(fmaf(x.x, a0, b0), 0.f);
    x.y = fmaxf(fmaf(x.y, a1, b1), 0.f);
    x.z = fmaxf(fmaf(x.z, a2, b2), 0.f);
    x.w = fmaxf(fmaf(x.w, a3, b3), 0.f);
    ((float4*)g_ft)[i4] = x;
}

// ---------------- cumtrapz along w ----------------
__global__ void k_cumx()
{
    const int nh = blockIdx.x;
    const int c  = threadIdx.x;
    size_t base = ((size_t)nh * WW) * CH + c;
    float prev = g_ft[base];
    float u = 0.f;
    g_Ux[base] = 0.f;
    for (int w = 1; w < WW; ++w) {
        float f = g_ft[base + (size_t)w * CH];
        u += 0.5f * (prev + f);
        g_Ux[base + (size_t)w * CH] = u;
        prev = f;
    }
}

// ---------------- cumtrapz along h ----------------
__global__ void k_cumy()
{
    const int nw = blockIdx.x;
    const int n  = nw / WW;
    const int w  = nw - n * WW;
    const int c  = threadIdx.x;
    size_t base   = ((size_t)n * HWSZ + w) * CH + c;
    size_t stride = (size_t)WW * CH;
    float pf = g_ft[base], pu = g_Ux[base];
    float uy = 0.f, tt = 0.f;
    g_Uy[base] = 0.f;
    g_T[base]  = 0.f;
    for (int hh = 1; hh < HH; ++hh) {
        float f = g_ft[base + hh * stride];
        float u = g_Ux[base + hh * stride];
        uy += 0.5f * (pf + f);
        tt += 0.5f * (pu + u);
        g_Uy[base + hh * stride] = uy;
        g_T [base + hh * stride] = tt;
        pf = f; pu = u;
    }
}

// ---------------- PrRoI pooling (+ FC-stat zeroing) ----------------
__global__ void k_pool(const float* __restrict__ props)
{
    const int p = blockIdx.x;
    const int c = threadIdx.x;
    if (p == 0) { g_fsum[c] = 0.f; g_fsq[c] = 0.f; }
    const float px = __ldg(&props[p * 4 + 0]);
    const float py = __ldg(&props[p * 4 + 1]);
    const float pw = __ldg(&props[p * 4 + 2]);
    const float ph = __ldg(&props[p * 4 + 3]);
    const float x1 = px * 20.f;
    const float y1 = py * 20.f;
    const float x2 = (px + pw) * 20.f;
    const float y2 = (py + ph) * 20.f;
    const float bw = (x2 - x1) * 0.25f;
    const float bh = (y2 - y1) * 0.25f;

    int   wx[5], hy[5];
    float px0[5], px1[5], py0[5], py1[5];
#pragma unroll
    for (int i = 0; i < 5; ++i) {
        float xs = fminf(fmaxf(x1 + bw * (float)i, 0.f), 35.f);
        int w0 = min((int)floorf(xs), 34);
        float sx = xs - (float)w0;
        float q = 0.5f * sx * sx;
        px1[i] = q; px0[i] = sx - q; wx[i] = w0;

        float ys = fminf(fmaxf(y1 + bh * (float)i, 0.f), 35.f);
        int h0 = min((int)floorf(ys), 34);
        float sy = ys - (float)h0;
        float r = 0.5f * sy * sy;
        py1[i] = r; py0[i] = sy - r; hy[i] = h0;
    }

    const int b = p >> 4;
    float G[5][5];
#pragma unroll
    for (int iy = 0; iy < 5; ++iy) {
#pragma unroll
        for (int ix = 0; ix < 5; ++ix) {
            size_t i00 = (((size_t)b * HH + hy[iy]) * WW + wx[ix]) * CH + c;
            size_t i01 = i00 + CH;
            size_t i10 = i00 + (size_t)WW * CH;
            size_t i11 = i10 + CH;
            G[iy][ix] = g_T[i00]
                      + g_Uy[i00] * px0[ix] + g_Uy[i01] * px1[ix]
                      + py0[iy] * (g_Ux[i00] + g_ft[i00] * px0[ix] + g_ft[i01] * px1[ix])
                      + py1[iy] * (g_Ux[i10] + g_ft[i10] * px0[ix] + g_ft[i11] * px1[ix]);
        }
    }
    const float area = bw * bh;
    const float inv  = (area > 1e-8f) ? (1.f / fmaxf(area, 1e-8f)) : 0.f;
    float* out = g_rf + (size_t)p * FCK + c * 16;
#pragma unroll
    for (int iy = 0; iy < 4; ++iy)
#pragma unroll
        for (int ix = 0; ix < 4; ++ix)
            out[iy * 4 + ix] =
                (G[iy + 1][ix + 1] - G[iy][ix + 1] - G[iy + 1][ix] + G[iy][ix]) * inv;
}

// ---------------- FC GEMM + fused stats ----------------
__global__ void __launch_bounds__(256) k_fc(const float* __restrict__ Wfc,
                                            const float* __restrict__ bias)
{
    __shared__ float As[16][65];
    __shared__ float Bs[16][65];
    __shared__ float sRed[128];

    const int tid = threadIdx.x;
    const int mt  = blockIdx.x * 64;
    const int nt  = blockIdx.y * 64;
    const int lr  = tid >> 2;
    const int lk  = (tid & 3) * 4;
    const int tm  = tid & 15;
    const int tn  = tid >> 4;

    float acc[4][4];
#pragma unroll
    for (int i = 0; i < 4; ++i)
#pragma unroll
        for (int j = 0; j < 4; ++j) acc[i][j] = 0.f;

    for (int kc = 0; kc < FCK / 16; ++kc) {
        float4 av = *(const float4*)&g_rf[(size_t)(mt + lr) * FCK + kc * 16 + lk];
        float4 bv = *(const float4*)&Wfc [(size_t)(nt + lr) * FCK + kc * 16 + lk];
        __syncthreads();
        As[lk + 0][lr] = av.x; As[lk + 1][lr] = av.y;
        As[lk + 2][lr] = av.z; As[lk + 3][lr] = av.w;
        Bs[lk + 0][lr] = bv.x; Bs[lk + 1][lr] = bv.y;
        Bs[lk + 2][lr] = bv.z; Bs[lk + 3][lr] = bv.w;
        __syncthreads();
#pragma unroll
        for (int kk = 0; kk < 16; ++kk) {
            float a[4], b[4];
#pragma unroll
            for (int i = 0; i < 4; ++i) a[i] = As[kk][tm + 16 * i];
#pragma unroll
            for (int j = 0; j < 4; ++j) b[j] = Bs[kk][tn * 4 + j];
#pragma unroll
            for (int i = 0; i < 4; ++i)
#pragma unroll
                for (int j = 0; j < 4; ++j)
                    acc[i][j] = fmaf(a[i], b[j], acc[i][j]);
        }
    }

    float s1a[4], s2a[4];
#pragma unroll
    for (int j = 0; j < 4; ++j) {
        const int c = nt + tn * 4 + j;
        const float bv = __ldg(&bias[c]);
        float s1 = 0.f, s2 = 0.f;
#pragma unroll
        for (int i = 0; i < 4; ++i) {
            const int m = mt + tm + 16 * i;
            float v = acc[i][j] + bv;
            g_fc[(size_t)m * CH + c] = v;
            s1 += v;
            s2 += v * v;
        }
        s1a[j] = s1; s2a[j] = s2;
    }
    __syncthreads();
    if (tid < 128) sRed[tid] = 0.f;
    __syncthreads();
#pragma unroll
    for (int j = 0; j < 4; ++j) {
        const int cl = tn * 4 + j;
        atomicAdd(&sRed[cl], s1a[j]);
        atomicAdd(&sRed[64 + cl], s2a[j]);
    }
    __syncthreads();
    if (tid < 64) {
        atomicAdd(&g_fsum[nt + tid], sRed[tid]);
        atomicAdd(&g_fsq [nt + tid], sRed[64 + tid]);
    }
}

// ---------------- FC BN + ReLU + IoU head ----------------
__global__ void k_fcbn_iou(const float* __restrict__ gm,
                           const float* __restrict__ bt,
                           const float* __restrict__ iw,
                           const float* __restrict__ ib,
                           float* __restrict__ out)
{
    __shared__ float sred[8];
    const int p = blockIdx.x;
    const int c = threadIdx.x;
    const float invN = 1.f / (float)NROI;
    float m  = g_fsum[c] * invN;
    float v  = g_fsq[c] * invN - m * m;
    float sc = rsqrtf(v + EPS_BN) * __ldg(&gm[c]);
    float sh = __ldg(&bt[c]) - m * sc;
    float x  = fmaxf(fmaf(g_fc[(size_t)p * CH + c], sc, sh), 0.f);
    float t  = x * __ldg(&iw[c]);
#pragma unroll
    for (int o = 16; o; o >>= 1) t += __shfl_xor_sync(0xffffffffu, t, o);
    if ((c & 31) == 0) sred[c >> 5] = t;
    __syncthreads();
    if (c == 0) {
        float s = 0.f;
#pragma unroll
        for (int i = 0; i < 8; ++i) s += sred[i];
        out[p] = s + __ldg(&ib[0]);
    }
}

// ---------------- launch sequence ----------------
extern "C" void kernel_launch(void* const* d_in, const int* in_sizes, int n_in,
                              void* d_out, int out_size)
{
    const float* feat  = (const float*)d_in[0];
    const float* props = (const float*)d_in[1];
    const float* c1w = (const float*)d_in[2];
    const float* c1b = (const float*)d_in[3];
    const float* b1g = (const float*)d_in[4];
    const float* b1b = (const float*)d_in[5];
    const float* c2w = (const float*)d_in[6];
    const float* c2b = (const float*)d_in[7];
    const float* b2g = (const float*)d_in[8];
    const float* b2b = (const float*)d_in[9];
    const float* c3w = (const float*)d_in[10];
    const float* c3b = (const float*)d_in[11];
    const float* b3g = (const float*)d_in[12];
    const float* b3b = (const float*)d_in[13];
    const float* fcw = (const float*)d_in[14];
    const float* fcb = (const float*)d_in[15];
    const float* fbg = (const float*)d_in[16];
    const float* fbb = (const float*)d_in[17];
    const float* iw  = (const float*)d_in[18];
    const float* ib  = (const float*)d_in[19];
    float* out = (float*)d_out;

    const int CONV_SMEM = 3 * STG_B;   // 98304 B per CTA, 2 CTAs/SM
    cudaFuncSetAttribute(k_conv_m, cudaFuncAttributeMaxDynamicSharedMemorySize, CONV_SMEM);

    const dim3 convGrid(MTOT / 128, 2);
    const int  wpBlocks = NK2;                  // 1152
    const int  spBlocks = MTOT * 8 / 256;       // 1296
    const int  bnBlocks = (MTOT * CH / 4) / 256;

    // conv1  (k_wprep zeroes conv stats in block 0)
    k_wprep<<<wpBlocks, 256>>>(c1w);
    k_cvtA_t<<<dim3(8, NIMG, 41), dim3(32, 8)>>>(feat);
    k_conv_m<<<convGrid, 128, CONV_SMEM>>>(c1b);
    k_bnrelu_split<<<spBlocks, 256>>>(b1g, b1b);
    // conv2
    k_wprep<<<wpBlocks, 256>>>(c2w);
    k_conv_m<<<convGrid, 128, CONV_SMEM>>>(c2b);
    k_bnrelu_split<<<spBlocks, 256>>>(b2g, b2b);
    // conv3
    k_wprep<<<wpBlocks, 256>>>(c3w);
    k_conv_m<<<convGrid, 128, CONV_SMEM>>>(c3b);
    k_bnrelu_final<<<bnBlocks, 256>>>(b3g, b3b);

    // integral images (NHWC, g_ft ready)
    k_cumx<<<NIMG * HH, 256>>>();
    k_cumy<<<NIMG * WW, 256>>>();

    // PrRoI pooling (zeroes FC stats in block 0)
    k_pool<<<NROI, 256>>>(props);

    // FC + BN + IoU
    k_fc<<<dim3(NROI / 64, CH / 64), 256>>>(fcw, fcb);
    k_fcbn_iou<<<NROI, 256>>>(fbg, fbb, iw, ib, out);
}

// round 11
// speedup vs baseline: 1.1602x; 1.1602x over previous
#include <cuda_runtime.h>
#include <cuda_bf16.h>
#include <cstdint>

// ---------------- problem constants ----------------
#define NIMG 32
#define CH   256
#define HH   36
#define WW   36
#define HWSZ 1296
#define MTOT (NIMG*HWSZ)   // 41472
#define KTOT (CH*9)        // 2304
#define NK2  (KTOT/2)      // 1152
#define NROI 512
#define FCK  4096
#define EPS_BN 1e-5f
#define CHW  (CH*HWSZ)

// ---------------- scratch ----------------
__device__ float    g_bufA[MTOT*CH];        // conv output, NHWC fp32
__device__ uint32_t g_aH[128*MTOT];         // activations [ci2][M] bf16x2 hi
__device__ uint32_t g_aL[128*MTOT];         // lo residual
__device__ uint32_t g_wbH[NK2*CH];          // weights [k2][n] bf16x2 hi (k = tap*256+ci)
__device__ uint32_t g_wbL[NK2*CH];
__device__ float g_ft [MTOT*CH];            // NHWC feat (pool phase)
__device__ float g_Ux [MTOT*CH];
__device__ float g_Uy [MTOT*CH];
__device__ float g_T  [MTOT*CH];
__device__ float g_rf [NROI*FCK];
__device__ float g_fc [NROI*CH];
__device__ float g_sum[CH], g_sq[CH];
__device__ float g_fsum[CH], g_fsq[CH];

// ---------------- helpers ----------------
__device__ __forceinline__ uint32_t smem_u32(const void* p) {
    uint32_t a;
    asm("{ .reg .u64 t; cvta.to.shared.u64 t, %1; cvt.u32.u64 %0, t; }" : "=r"(a) : "l"(p));
    return a;
}
__device__ __forceinline__ void bfsplit(float v, uint16_t& hi, uint16_t& lo) {
    __nv_bfloat16 h = __float2bfloat16(v);
    __nv_bfloat16 l = __float2bfloat16(v - __bfloat162float(h));
    hi = __bfloat16_as_ushort(h);
    lo = __bfloat16_as_ushort(l);
}
__device__ __forceinline__ void mma16(float d[4], const uint32_t a[4], const uint32_t b[2]) {
    asm volatile("mma.sync.aligned.m16n8k16.row.col.f32.bf16.bf16.f32 "
        "{%0,%1,%2,%3},{%4,%5,%6,%7},{%8,%9},{%0,%1,%2,%3};"
        : "+f"(d[0]), "+f"(d[1]), "+f"(d[2]), "+f"(d[3])
        : "r"(a[0]), "r"(a[1]), "r"(a[2]), "r"(a[3]), "r"(b[0]), "r"(b[1]));
}
__device__ __forceinline__ void cp4(uint32_t dst, const void* src, uint32_t sz) {
    asm volatile("cp.async.ca.shared.global [%0], [%1], 4, %2;" :: "r"(dst), "l"(src), "r"(sz));
}
__device__ __forceinline__ void cp16(uint32_t dst, const void* src) {
    asm volatile("cp.async.cg.shared.global [%0], [%1], 16;" :: "r"(dst), "l"(src));
}
#define CP_COMMIT() asm volatile("cp.async.commit_group;" ::: "memory")
#define CP_WAIT1()  asm volatile("cp.async.wait_group 1;"  ::: "memory")

// ---------------- weight prep: [k2][n] bf16-pair split + conv-stat zeroing ----------------
__global__ void k_wprep(const float* __restrict__ W) {
    int idx = blockIdx.x * 256 + threadIdx.x;   // idx = k2*256 + n
    if (blockIdx.x == 0) {
        g_sum[threadIdx.x] = 0.f;
        g_sq [threadIdx.x] = 0.f;
    }
    int n   = idx & 255;
    int k2  = idx >> 8;
    int ci2 = k2 & 127;
    int tap = k2 >> 7;
    float v0 = __ldg(&W[(size_t)n * KTOT + (2 * ci2)     * 9 + tap]);
    float v1 = __ldg(&W[(size_t)n * KTOT + (2 * ci2 + 1) * 9 + tap]);
    uint16_t h0, l0, h1, l1;
    bfsplit(v0, h0, l0);
    bfsplit(v1, h1, l1);
    g_wbH[idx] = ((uint32_t)h1 << 16) | h0;
    g_wbL[idx] = ((uint32_t)l1 << 16) | l0;
}

// ---------------- conv1 input prep: NCHW feat -> [ci2][M] bf16-pair split ----------------
__global__ void k_cvtA(const float* __restrict__ feat) {
    int i   = blockIdx.x * 256 + threadIdx.x;   // i = ci2*MTOT + m
    int ci2 = i / MTOT;
    int m   = i - ci2 * MTOT;
    int nimg = m / HWSZ;
    int hw   = m - nimg * HWSZ;
    const size_t s = ((size_t)nimg * CH + 2 * ci2) * HWSZ + hw;
    float v0 = __ldg(&feat[s]);
    float v1 = __ldg(&feat[s + HWSZ]);
    uint16_t h0, l0, h1, l1;
    bfsplit(v0, h0, l0);
    bfsplit(v1, h1, l1);
    g_aH[i] = ((uint32_t)h1 << 16) | h0;
    g_aL[i] = ((uint32_t)l1 << 16) | l0;
}

// ===== 3-stage pipelined bf16x3 m16n8k16 implicit-GEMM conv, 2 CTAs/SM =====
// EXACT R7 mainloop; epilogue stores NHWC (coalesced 32B groups).
#define NCHNK 72
#define STG_W 8704           // stage size in words
#define STG_B 34816          // stage size in bytes

__global__ void __launch_bounds__(128, 2) k_conv_m(const float* __restrict__ bias)
{
    extern __shared__ uint32_t dynu[];
    __shared__ float sRed1[128], sRed2[128];
    const uint32_t sb = smem_u32(dynu);

    const int tid  = threadIdx.x;
    const int lane = tid & 31, wid = tid >> 5;
    const int mt   = blockIdx.x * 128, nt = blockIdx.y * 128;
    const int wm   = (wid >> 1) * 64, wn = (wid & 1) * 64;
    const int g    = lane >> 2, c0 = lane & 3;

    sRed1[tid] = 0.f; sRed2[tid] = 0.f;

    // A-fill mapping: thread owns m = mt + tid; 16 k2 per chunk, stride MTOT
    const int mA    = mt + tid;
    const int nimgA = mA / HWSZ;
    const int remA  = mA - nimgA * HWSZ;
    const int hA    = remA / WW;
    const int wA    = remA - hA * WW;
    const int aimg  = nimgA * HWSZ;

    // B-fill mapping: rows bkrow+4j, 16B of n
    const int bkrow = tid >> 5;            // 0..3
    const int bn4   = (tid & 31) * 4;      // word offset in n

    float acc[4][8][4];
#pragma unroll
    for (int a = 0; a < 4; ++a)
#pragma unroll
        for (int b = 0; b < 8; ++b)
#pragma unroll
            for (int c = 0; c < 4; ++c) acc[a][b][c] = 0.f;

    auto fillA = [&](int st, int ch, int half) {
        const int tap = ch >> 3, cc = ch & 7;
        const int hh = hA + tap / 3 - 1, ww = wA + tap % 3 - 1;
        const bool valid = ((unsigned)hh < HH) && ((unsigned)ww < WW);
        const uint32_t sz = valid ? 4u : 0u;
        const uint32_t* p = (half ? g_aL : g_aH)
                          + (size_t)(cc * 16) * MTOT + aimg + (valid ? hh * WW + ww : 0);
        uint32_t d = sb + st * STG_B + half * 8704 + tid * 4;
#pragma unroll
        for (int i = 0; i < 16; ++i) {
            cp4(d, p, sz);
            p += MTOT; d += 544;
        }
    };
    auto fillB = [&](int st, int ch, int half) {
        const int tap = ch >> 3, cc = ch & 7;
        const int kb2 = tap * 128 + cc * 16;
        const uint32_t* Wp = half ? g_wbL : g_wbH;
        uint32_t d = sb + st * STG_B + 17408 + half * 8704 + bkrow * 544 + bn4 * 4;
#pragma unroll
        for (int j = 0; j < 4; ++j)
            cp16(d + j * 2176, Wp + (size_t)(kb2 + bkrow + j * 4) * 256 + nt + bn4);
    };

    // prologue: stages 0 and 1 (chunks 0 and 1)
    fillA(0, 0, 0); fillA(0, 0, 1); fillB(0, 0, 0); fillB(0, 0, 1); CP_COMMIT();
    fillA(1, 1, 0); fillA(1, 1, 1); fillB(1, 1, 0); fillB(1, 1, 1); CP_COMMIT();

    int stc = 0, stf = 2;
    for (int ch = 0; ch < NCHNK; ++ch) {
        CP_WAIT1();
        __syncthreads();
        const bool pf = (ch + 2) < NCHNK;
        const uint32_t* base = dynu + stc * STG_W;
        const uint32_t* AsH = base;
        const uint32_t* AsL = base + 2176;
        const uint32_t* BsH = base + 4352;
        const uint32_t* BsL = base + 6528;
#pragma unroll
        for (int kk = 0; kk < 2; ++kk) {
            if (pf) {
                if (kk == 0) { fillA(stf, ch + 2, 0); fillA(stf, ch + 2, 1); }
                else         { fillB(stf, ch + 2, 0); fillB(stf, ch + 2, 1); }
            }
            const int r0 = (kk * 8 + c0) * 136;
            const int r1 = r0 + 4 * 136;
            uint32_t ah[4][4], al[4][4], bh[8][2], bl[8][2];
#pragma unroll
            for (int mf = 0; mf < 4; ++mf) {
                const int col = wm + mf * 16 + g;
                ah[mf][0] = AsH[r0 + col];
                ah[mf][1] = AsH[r0 + col + 8];
                ah[mf][2] = AsH[r1 + col];
                ah[mf][3] = AsH[r1 + col + 8];
                al[mf][0] = AsL[r0 + col];
                al[mf][1] = AsL[r0 + col + 8];
                al[mf][2] = AsL[r1 + col];
                al[mf][3] = AsL[r1 + col + 8];
            }
#pragma unroll
            for (int nf = 0; nf < 8; ++nf) {
                const int q0 = r0 + wn + nf * 8 + g;
                const int q1 = q0 + 4 * 136;
                bh[nf][0] = BsH[q0];
                bh[nf][1] = BsH[q1];
                bl[nf][0] = BsL[q0];
                bl[nf][1] = BsL[q1];
            }
#pragma unroll
            for (int mf = 0; mf < 4; ++mf)
#pragma unroll
                for (int nf = 0; nf < 8; ++nf) {
                    mma16(acc[mf][nf], ah[mf], bh[nf]);
                    mma16(acc[mf][nf], ah[mf], bl[nf]);
                    mma16(acc[mf][nf], al[mf], bh[nf]);
                }
        }
        CP_COMMIT();
        stc = (stc == 2) ? 0 : stc + 1;
        stf = (stf == 2) ? 0 : stf + 1;
    }

    // ---------------- epilogue: bias, NHWC store (coalesced), fused stats ----------------
    float s1[16], s2[16];
#pragma unroll
    for (int i = 0; i < 16; ++i) { s1[i] = 0.f; s2[i] = 0.f; }

#pragma unroll
    for (int mf = 0; mf < 4; ++mf) {
#pragma unroll
        for (int rr = 0; rr < 2; ++rr) {
            const int m = mt + wm + mf * 16 + g + rr * 8;
            float* orow = g_bufA + (size_t)m * CH;
#pragma unroll
            for (int nf = 0; nf < 8; ++nf) {
                const int c = nt + wn + nf * 8 + c0 * 2;
                const float v0 = acc[mf][nf][rr * 2]     + __ldg(&bias[c]);
                const float v1 = acc[mf][nf][rr * 2 + 1] + __ldg(&bias[c + 1]);
                *(float2*)(orow + c) = make_float2(v0, v1);
                s1[nf * 2]     += v0; s2[nf * 2]     += v0 * v0;
                s1[nf * 2 + 1] += v1; s2[nf * 2 + 1] += v1 * v1;
            }
        }
    }
    __syncthreads();
#pragma unroll
    for (int nf = 0; nf < 8; ++nf) {
        const int cl = wn + nf * 8 + c0 * 2;
        atomicAdd(&sRed1[cl],     s1[nf * 2]);
        atomicAdd(&sRed2[cl],     s2[nf * 2]);
        atomicAdd(&sRed1[cl + 1], s1[nf * 2 + 1]);
        atomicAdd(&sRed2[cl + 1], s2[nf * 2 + 1]);
    }
    __syncthreads();
    atomicAdd(&g_sum[nt + tid], sRed1[tid]);
    atomicAdd(&g_sq [nt + tid], sRed2[tid]);
}

// ---------------- BN+ReLU+split via 32x32 smem transpose: NHWC -> [ci2][M] ----------------
// grid (8, NIMG, 41), block (32, 8): reads coalesced (32 consecutive c),
// writes coalesced (32 consecutive m).
__global__ void k_bnsplit_t(const float* __restrict__ gm,
                            const float* __restrict__ bt)
{
    __shared__ float s[32][33];
    __shared__ float ssc[32], ssh[32];
    const int cb = blockIdx.x;
    const int n  = blockIdx.y;
    const int pb = blockIdx.z;
    const int tx = threadIdx.x, ty = threadIdx.y;
    const int tid = ty * 32 + tx;
    const float invN = 1.0f / (float)MTOT;

    if (tid < 32) {
        const int c = cb * 32 + tid;
        float m = g_sum[c] * invN;
        float v = g_sq[c] * invN - m * m;
        float sc = rsqrtf(v + EPS_BN) * __ldg(&gm[c]);
        ssc[tid] = sc;
        ssh[tid] = __ldg(&bt[c]) - m * sc;
    }
    __syncthreads();

    const int p0 = pb * 32;
#pragma unroll
    for (int yy = 0; yy < 4; ++yy) {
        const int p = p0 + ty + yy * 8;
        float x = (p < HWSZ)
                ? g_bufA[((size_t)n * HWSZ + p) * CH + cb * 32 + tx] : 0.f;
        s[tx][ty + yy * 8] = fmaxf(fmaf(x, ssc[tx], ssh[tx]), 0.f);
    }
    __syncthreads();
#pragma unroll
    for (int yy = 0; yy < 2; ++yy) {
        const int ci2l = ty + yy * 8;       // 0..15
        const int p = p0 + tx;
        if (p < HWSZ) {
            float y0 = s[2 * ci2l][tx];
            float y1 = s[2 * ci2l + 1][tx];
            uint16_t h0, l0, h1, l1;
            bfsplit(y0, h0, l0);
            bfsplit(y1, h1, l1);
            const size_t i = (size_t)(cb * 16 + ci2l) * MTOT + (size_t)n * HWSZ + p;
            g_aH[i] = ((uint32_t)h1 << 16) | h0;
            g_aL[i] = ((uint32_t)l1 << 16) | l0;
        }
    }
}

// ---------------- final BN + ReLU: NHWC -> g_ft NHWC (elementwise, coalesced) ----------------
__global__ void k_bnrelu_final(const float* __restrict__ gm,
                               const float* __restrict__ bt)
{
    const float invN = 1.0f / (float)MTOT;
    int i4 = blockIdx.x * blockDim.x + threadIdx.x;
    int c  = (i4 * 4) & (CH - 1);
    float4 x = ((const float4*)g_bufA)[i4];
    float m0 = g_sum[c] * invN, vv0 = g_sq[c] * invN - m0 * m0;
    float a0 = rsqrtf(vv0 + EPS_BN) * __ldg(&gm[c]);
    float b0 = __ldg(&bt[c]) - m0 * a0;
    float m1 = g_sum[c+1] * invN, vv1 = g_sq[c+1] * invN - m1 * m1;
    float a1 = rsqrtf(vv1 + EPS_BN) * __ldg(&gm[c+1]);
    float b1 = __ldg(&bt[c+1]) - m1 * a1;
    float m2 = g_sum[c+2] * invN, vv2 = g_sq[c+2] * invN - m2 * m2;
    float a2 = rsqrtf(vv2 + EPS_BN) * __ldg(&gm[c+2]);
    float b2 = __ldg(&bt[c+2]) - m2 * a2;
    float m3 = g_sum[c+3] * invN, vv3 = g_sq[c+3] * invN - m3 * m3;
    float a3 = rsqrtf(vv3 + EPS_BN) * __ldg(&gm[c+3]);
    float b3 = __ldg(&bt[c+3]) - m3 * a3;
    x.x = fmaxf(fmaf(x.x, a0, b0), 0.f);
    x.y = fmaxf(fmaf(x.y, a1, b1), 0.f);
    x.z = fmaxf(fmaf(x.z, a2, b2), 0.f);
    x.w = fmaxf(fmaf(x.w, a3, b3), 0.f);
    ((float4*)g_ft)[i4] = x;
}

// ---------------- cumtrapz along w ----------------
__global__ void k_cumx()
{
    const int nh = blockIdx.x;
    const int c  = threadIdx.x;
    size_t base = ((size_t)nh * WW) * CH + c;
    float prev = g_ft[base];
    float u = 0.f;
    g_Ux[base] = 0.f;
    for (int w = 1; w < WW; ++w) {
        float f = g_ft[base + (size_t)w * CH];
        u += 0.5f * (prev + f);
        g_Ux[base + (size_t)w * CH] = u;
        prev = f;
    }
}

// ---------------- cumtrapz along h ----------------
__global__ void k_cumy()
{
    const int nw = blockIdx.x;
    const int n  = nw / WW;
    const int w  = nw - n * WW;
    const int c  = threadIdx.x;
    size_t base   = ((size_t)n * HWSZ + w) * CH + c;
    size_t stride = (size_t)WW * CH;
    float pf = g_ft[base], pu = g_Ux[base];
    float uy = 0.f, tt = 0.f;
    g_Uy[base] = 0.f;
    g_T[base]  = 0.f;
    for (int hh = 1; hh < HH; ++hh) {
        float f = g_ft[base + hh * stride];
        float u = g_Ux[base + hh * stride];
        uy += 0.5f * (pf + f);
        tt += 0.5f * (pu + u);
        g_Uy[base + hh * stride] = uy;
        g_T [base + hh * stride] = tt;
        pf = f; pu = u;
    }
}

// ---------------- PrRoI pooling (+ FC-stat zeroing) ----------------
__global__ void k_pool(const float* __restrict__ props)
{
    const int p = blockIdx.x;
    const int c = threadIdx.x;
    if (p == 0) { g_fsum[c] = 0.f; g_fsq[c] = 0.f; }
    const float px = __ldg(&props[p * 4 + 0]);
    const float py = __ldg(&props[p * 4 + 1]);
    const float pw = __ldg(&props[p * 4 + 2]);
    const float ph = __ldg(&props[p * 4 + 3]);
    const float x1 = px * 20.f;
    const float y1 = py * 20.f;
    const float x2 = (px + pw) * 20.f;
    const float y2 = (py + ph) * 20.f;
    const float bw = (x2 - x1) * 0.25f;
    const float bh = (y2 - y1) * 0.25f;

    int   wx[5], hy[5];
    float px0[5], px1[5], py0[5], py1[5];
#pragma unroll
    for (int i = 0; i < 5; ++i) {
        float xs = fminf(fmaxf(x1 + bw * (float)i, 0.f), 35.f);
        int w0 = min((int)floorf(xs), 34);
        float sx = xs - (float)w0;
        float q = 0.5f * sx * sx;
        px1[i] = q; px0[i] = sx - q; wx[i] = w0;

        float ys = fminf(fmaxf(y1 + bh * (float)i, 0.f), 35.f);
        int h0 = min((int)floorf(ys), 34);
        float sy = ys - (float)h0;
        float r = 0.5f * sy * sy;
        py1[i] = r; py0[i] = sy - r; hy[i] = h0;
    }

    const int b = p >> 4;
    float G[5][5];
#pragma unroll
    for (int iy = 0; iy < 5; ++iy) {
#pragma unroll
        for (int ix = 0; ix < 5; ++ix) {
            size_t i00 = (((size_t)b * HH + hy[iy]) * WW + wx[ix]) * CH + c;
            size_t i01 = i00 + CH;
            size_t i10 = i00 + (size_t)WW * CH;
            size_t i11 = i10 + CH;
            G[iy][ix] = g_T[i00]
                      + g_Uy[i00] * px0[ix] + g_Uy[i01] * px1[ix]
                      + py0[iy] * (g_Ux[i00] + g_ft[i00] * px0[ix] + g_ft[i01] * px1[ix])
                      + py1[iy] * (g_Ux[i10] + g_ft[i10] * px0[ix] + g_ft[i11] * px1[ix]);
        }
    }
    const float area = bw * bh;
    const float inv  = (area > 1e-8f) ? (1.f / fmaxf(area, 1e-8f)) : 0.f;
    float* out = g_rf + (size_t)p * FCK + c * 16;
#pragma unroll
    for (int iy = 0; iy < 4; ++iy)
#pragma unroll
        for (int ix = 0; ix < 4; ++ix)
            out[iy * 4 + ix] =
                (G[iy + 1][ix + 1] - G[iy][ix + 1] - G[iy + 1][ix] + G[iy][ix]) * inv;
}

// ---------------- FC GEMM + fused stats ----------------
__global__ void __launch_bounds__(256) k_fc(const float* __restrict__ Wfc,
                                            const float* __restrict__ bias)
{
    __shared__ float As[16][65];
    __shared__ float Bs[16][65];
    __shared__ float sRed[128];

    const int tid = threadIdx.x;
    const int mt  = blockIdx.x * 64;
    const int nt  = blockIdx.y * 64;
    const int lr  = tid >> 2;
    const int lk  = (tid & 3) * 4;
    const int tm  = tid & 15;
    const int tn  = tid >> 4;

    float acc[4][4];
#pragma unroll
    for (int i = 0; i < 4; ++i)
#pragma unroll
        for (int j = 0; j < 4; ++j) acc[i][j] = 0.f;

    for (int kc = 0; kc < FCK / 16; ++kc) {
        float4 av = *(const float4*)&g_rf[(size_t)(mt + lr) * FCK + kc * 16 + lk];
        float4 bv = *(const float4*)&Wfc [(size_t)(nt + lr) * FCK + kc * 16 + lk];
        __syncthreads();
        As[lk + 0][lr] = av.x; As[lk + 1][lr] = av.y;
        As[lk + 2][lr] = av.z; As[lk + 3][lr] = av.w;
        Bs[lk + 0][lr] = bv.x; Bs[lk + 1][lr] = bv.y;
        Bs[lk + 2][lr] = bv.z; Bs[lk + 3][lr] = bv.w;
        __syncthreads();
#pragma unroll
        for (int kk = 0; kk < 16; ++kk) {
            float a[4], b[4];
#pragma unroll
            for (int i = 0; i < 4; ++i) a[i] = As[kk][tm + 16 * i];
#pragma unroll
            for (int j = 0; j < 4; ++j) b[j] = Bs[kk][tn * 4 + j];
#pragma unroll
            for (int i = 0; i < 4; ++i)
#pragma unroll
                for (int j = 0; j < 4; ++j)
                    acc[i][j] = fmaf(a[i], b[j], acc[i][j]);
        }
    }

    float s1a[4], s2a[4];
#pragma unroll
    for (int j = 0; j < 4; ++j) {
        const int c = nt + tn * 4 + j;
        const float bv = __ldg(&bias[c]);
        float s1 = 0.f, s2 = 0.f;
#pragma unroll
        for (int i = 0; i < 4; ++i) {
            const int m = mt + tm + 16 * i;
            float v = acc[i][j] + bv;
            g_fc[(size_t)m * CH + c] = v;
            s1 += v;
            s2 += v * v;
        }
        s1a[j] = s1; s2a[j] = s2;
    }
    __syncthreads();
    if (tid < 128) sRed[tid] = 0.f;
    __syncthreads();
#pragma unroll
    for (int j = 0; j < 4; ++j) {
        const int cl = tn * 4 + j;
        atomicAdd(&sRed[cl], s1a[j]);
        atomicAdd(&sRed[64 + cl], s2a[j]);
    }
    __syncthreads();
    if (tid < 64) {
        atomicAdd(&g_fsum[nt + tid], sRed[tid]);
        atomicAdd(&g_fsq [nt + tid], sRed[64 + tid]);
    }
}

// ---------------- FC BN + ReLU + IoU head ----------------
__global__ void k_fcbn_iou(const float* __restrict__ gm,
                           const float* __restrict__ bt,
                           const float* __restrict__ iw,
                           const float* __restrict__ ib,
                           float* __restrict__ out)
{
    __shared__ float sred[8];
    const int p = blockIdx.x;
    const int c = threadIdx.x;
    const float invN = 1.f / (float)NROI;
    float m  = g_fsum[c] * invN;
    float v  = g_fsq[c] * invN - m * m;
    float sc = rsqrtf(v + EPS_BN) * __ldg(&gm[c]);
    float sh = __ldg(&bt[c]) - m * sc;
    float x  = fmaxf(fmaf(g_fc[(size_t)p * CH + c], sc, sh), 0.f);
    float t  = x * __ldg(&iw[c]);
#pragma unroll
    for (int o = 16; o; o >>= 1) t += __shfl_xor_sync(0xffffffffu, t, o);
    if ((c & 31) == 0) sred[c >> 5] = t;
    __syncthreads();
    if (c == 0) {
        float s = 0.f;
#pragma unroll
        for (int i = 0; i < 8; ++i) s += sred[i];
        out[p] = s + __ldg(&ib[0]);
    }
}

// ---------------- launch sequence ----------------
extern "C" void kernel_launch(void* const* d_in, const int* in_sizes, int n_in,
                              void* d_out, int out_size)
{
    const float* feat  = (const float*)d_in[0];
    const float* props = (const float*)d_in[1];
    const float* c1w = (const float*)d_in[2];
    const float* c1b = (const float*)d_in[3];
    const float* b1g = (const float*)d_in[4];
    const float* b1b = (const float*)d_in[5];
    const float* c2w = (const float*)d_in[6];
    const float* c2b = (const float*)d_in[7];
    const float* b2g = (const float*)d_in[8];
    const float* b2b = (const float*)d_in[9];
    const float* c3w = (const float*)d_in[10];
    const float* c3b = (const float*)d_in[11];
    const float* b3g = (const float*)d_in[12];
    const float* b3b = (const float*)d_in[13];
    const float* fcw = (const float*)d_in[14];
    const float* fcb = (const float*)d_in[15];
    const float* fbg = (const float*)d_in[16];
    const float* fbb = (const float*)d_in[17];
    const float* iw  = (const float*)d_in[18];
    const float* ib  = (const float*)d_in[19];
    float* out = (float*)d_out;

    const int CONV_SMEM = 3 * STG_B;   // 104448 B per CTA, 2 CTAs/SM
    cudaFuncSetAttribute(k_conv_m, cudaFuncAttributeMaxDynamicSharedMemorySize, CONV_SMEM);

    const dim3 convGrid(MTOT / 128, 2);
    const int  wpBlocks = NK2;                  // 1152
    const int  spBlocks = 128 * MTOT / 256;     // 20736 (cvtA)
    const int  bnBlocks = (MTOT * CH / 4) / 256;

    // conv1  (k_wprep zeroes conv stats in block 0)
    k_wprep<<<wpBlocks, 256>>>(c1w);
    k_cvtA<<<spBlocks, 256>>>(feat);
    k_conv_m<<<convGrid, 128, CONV_SMEM>>>(c1b);
    k_bnsplit_t<<<dim3(8, NIMG, 41), dim3(32, 8)>>>(b1g, b1b);
    // conv2
    k_wprep<<<wpBlocks, 256>>>(c2w);
    k_conv_m<<<convGrid, 128, CONV_SMEM>>>(c2b);
    k_bnsplit_t<<<dim3(8, NIMG, 41), dim3(32, 8)>>>(b2g, b2b);
    // conv3
    k_wprep<<<wpBlocks, 256>>>(c3w);
    k_conv_m<<<convGrid, 128, CONV_SMEM>>>(c3b);
    k_bnrelu_final<<<bnBlocks, 256>>>(b3g, b3b);

    // integral images (NHWC, g_ft ready)
    k_cumx<<<NIMG * HH, 256>>>();
    k_cumy<<<NIMG * WW, 256>>>();

    // PrRoI pooling (zeroes FC stats in block 0)
    k_pool<<<NROI, 256>>>(props);

    // FC + BN + IoU
    k_fc<<<dim3(NROI / 64, CH / 64), 256>>>(fcw, fcb);
    k_fcbn_iou<<<NROI, 256>>>(fbg, fbb, iw, ib, out);
}

// round 12
// speedup vs baseline: 1.1636x; 1.0029x over previous
#include <cuda_runtime.h>
#include <cuda_bf16.h>
#include <cstdint>

// ---------------- problem constants ----------------
#define NIMG 32
#define CH   256
#define HH   36
#define WW   36
#define HWSZ 1296
#define MTOT (NIMG*HWSZ)   // 41472
#define KTOT (CH*9)        // 2304
#define NK2  (KTOT/2)      // 1152
#define NROI 512
#define FCK  4096
#define EPS_BN 1e-5f
#define CHW  (CH*HWSZ)

// ---------------- scratch ----------------
__device__ float    g_bufA[MTOT*CH];        // conv output, NHWC fp32
__device__ uint32_t g_aH[128*MTOT];         // activations [ci2][M] bf16x2 hi
__device__ uint32_t g_aL[128*MTOT];         // lo residual
__device__ uint32_t g_wbH[NK2*CH];          // weights [k2][n] bf16x2 hi (k = tap*256+ci)
__device__ uint32_t g_wbL[NK2*CH];
__device__ float g_ft [MTOT*CH];            // NHWC feat (pool phase)
__device__ float g_Ux [MTOT*CH];
__device__ float g_Uy [MTOT*CH];
__device__ float g_T  [MTOT*CH];
__device__ float g_rf [NROI*FCK];
__device__ float g_fc [NROI*CH];
__device__ float g_sum[CH], g_sq[CH];
__device__ float g_fsum[CH], g_fsq[CH];

// ---------------- helpers ----------------
__device__ __forceinline__ uint32_t smem_u32(const void* p) {
    uint32_t a;
    asm("{ .reg .u64 t; cvta.to.shared.u64 t, %1; cvt.u32.u64 %0, t; }" : "=r"(a) : "l"(p));
    return a;
}
__device__ __forceinline__ void bfsplit(float v, uint16_t& hi, uint16_t& lo) {
    __nv_bfloat16 h = __float2bfloat16(v);
    __nv_bfloat16 l = __float2bfloat16(v - __bfloat162float(h));
    hi = __bfloat16_as_ushort(h);
    lo = __bfloat16_as_ushort(l);
}
__device__ __forceinline__ void mma16(float d[4], const uint32_t a[4], const uint32_t b[2]) {
    asm volatile("mma.sync.aligned.m16n8k16.row.col.f32.bf16.bf16.f32 "
        "{%0,%1,%2,%3},{%4,%5,%6,%7},{%8,%9},{%0,%1,%2,%3};"
        : "+f"(d[0]), "+f"(d[1]), "+f"(d[2]), "+f"(d[3])
        : "r"(a[0]), "r"(a[1]), "r"(a[2]), "r"(a[3]), "r"(b[0]), "r"(b[1]));
}
__device__ __forceinline__ void cp4(uint32_t dst, const void* src, uint32_t sz) {
    asm volatile("cp.async.ca.shared.global [%0], [%1], 4, %2;" :: "r"(dst), "l"(src), "r"(sz));
}
__device__ __forceinline__ void cp16(uint32_t dst, const void* src) {
    asm volatile("cp.async.cg.shared.global [%0], [%1], 16;" :: "r"(dst), "l"(src));
}
#define CP_COMMIT() asm volatile("cp.async.commit_group;" ::: "memory")
#define CP_WAIT1()  asm volatile("cp.async.wait_group 1;"  ::: "memory")

// ---------------- weight prep: [k2][n] bf16-pair split + conv-stat zeroing ----------------
__global__ void k_wprep(const float* __restrict__ W) {
    int idx = blockIdx.x * 256 + threadIdx.x;   // idx = k2*256 + n
    if (blockIdx.x == 0) {
        g_sum[threadIdx.x] = 0.f;
        g_sq [threadIdx.x] = 0.f;
    }
    int n   = idx & 255;
    int k2  = idx >> 8;
    int ci2 = k2 & 127;
    int tap = k2 >> 7;
    float v0 = __ldg(&W[(size_t)n * KTOT + (2 * ci2)     * 9 + tap]);
    float v1 = __ldg(&W[(size_t)n * KTOT + (2 * ci2 + 1) * 9 + tap]);
    uint16_t h0, l0, h1, l1;
    bfsplit(v0, h0, l0);
    bfsplit(v1, h1, l1);
    g_wbH[idx] = ((uint32_t)h1 << 16) | h0;
    g_wbL[idx] = ((uint32_t)l1 << 16) | l0;
}

// ---------------- conv1 input prep: NCHW feat -> [ci2][M] bf16-pair split ----------------
__global__ void k_cvtA(const float* __restrict__ feat) {
    int i   = blockIdx.x * 256 + threadIdx.x;   // i = ci2*MTOT + m
    int ci2 = i / MTOT;
    int m   = i - ci2 * MTOT;
    int nimg = m / HWSZ;
    int hw   = m - nimg * HWSZ;
    const size_t s = ((size_t)nimg * CH + 2 * ci2) * HWSZ + hw;
    float v0 = __ldg(&feat[s]);
    float v1 = __ldg(&feat[s + HWSZ]);
    uint16_t h0, l0, h1, l1;
    bfsplit(v0, h0, l0);
    bfsplit(v1, h1, l1);
    g_aH[i] = ((uint32_t)h1 << 16) | h0;
    g_aL[i] = ((uint32_t)l1 << 16) | l0;
}

// ===== 3-stage pipelined bf16x3 m16n8k16 implicit-GEMM conv, 2 CTAs/SM =====
// R11 mainloop with PASS-SEPARATED MMA sweeps (dependency distance 1 -> 32).
#define NCHNK 72
#define STG_W 8704           // stage size in words
#define STG_B 34816          // stage size in bytes

__global__ void __launch_bounds__(128, 2) k_conv_m(const float* __restrict__ bias)
{
    extern __shared__ uint32_t dynu[];
    __shared__ float sRed1[128], sRed2[128];
    const uint32_t sb = smem_u32(dynu);

    const int tid  = threadIdx.x;
    const int lane = tid & 31, wid = tid >> 5;
    const int mt   = blockIdx.x * 128, nt = blockIdx.y * 128;
    const int wm   = (wid >> 1) * 64, wn = (wid & 1) * 64;
    const int g    = lane >> 2, c0 = lane & 3;

    sRed1[tid] = 0.f; sRed2[tid] = 0.f;

    // A-fill mapping: thread owns m = mt + tid; 16 k2 per chunk, stride MTOT
    const int mA    = mt + tid;
    const int nimgA = mA / HWSZ;
    const int remA  = mA - nimgA * HWSZ;
    const int hA    = remA / WW;
    const int wA    = remA - hA * WW;
    const int aimg  = nimgA * HWSZ;

    // B-fill mapping: rows bkrow+4j, 16B of n
    const int bkrow = tid >> 5;            // 0..3
    const int bn4   = (tid & 31) * 4;      // word offset in n

    float acc[4][8][4];
#pragma unroll
    for (int a = 0; a < 4; ++a)
#pragma unroll
        for (int b = 0; b < 8; ++b)
#pragma unroll
            for (int c = 0; c < 4; ++c) acc[a][b][c] = 0.f;

    auto fillA = [&](int st, int ch, int half) {
        const int tap = ch >> 3, cc = ch & 7;
        const int hh = hA + tap / 3 - 1, ww = wA + tap % 3 - 1;
        const bool valid = ((unsigned)hh < HH) && ((unsigned)ww < WW);
        const uint32_t sz = valid ? 4u : 0u;
        const uint32_t* p = (half ? g_aL : g_aH)
                          + (size_t)(cc * 16) * MTOT + aimg + (valid ? hh * WW + ww : 0);
        uint32_t d = sb + st * STG_B + half * 8704 + tid * 4;
#pragma unroll
        for (int i = 0; i < 16; ++i) {
            cp4(d, p, sz);
            p += MTOT; d += 544;
        }
    };
    auto fillB = [&](int st, int ch, int half) {
        const int tap = ch >> 3, cc = ch & 7;
        const int kb2 = tap * 128 + cc * 16;
        const uint32_t* Wp = half ? g_wbL : g_wbH;
        uint32_t d = sb + st * STG_B + 17408 + half * 8704 + bkrow * 544 + bn4 * 4;
#pragma unroll
        for (int j = 0; j < 4; ++j)
            cp16(d + j * 2176, Wp + (size_t)(kb2 + bkrow + j * 4) * 256 + nt + bn4);
    };

    // prologue: stages 0 and 1 (chunks 0 and 1)
    fillA(0, 0, 0); fillA(0, 0, 1); fillB(0, 0, 0); fillB(0, 0, 1); CP_COMMIT();
    fillA(1, 1, 0); fillA(1, 1, 1); fillB(1, 1, 0); fillB(1, 1, 1); CP_COMMIT();

    int stc = 0, stf = 2;
    for (int ch = 0; ch < NCHNK; ++ch) {
        CP_WAIT1();
        __syncthreads();
        const bool pf = (ch + 2) < NCHNK;
        const uint32_t* base = dynu + stc * STG_W;
        const uint32_t* AsH = base;
        const uint32_t* AsL = base + 2176;
        const uint32_t* BsH = base + 4352;
        const uint32_t* BsL = base + 6528;
#pragma unroll
        for (int kk = 0; kk < 2; ++kk) {
            if (pf) {
                if (kk == 0) { fillA(stf, ch + 2, 0); fillA(stf, ch + 2, 1); }
                else         { fillB(stf, ch + 2, 0); fillB(stf, ch + 2, 1); }
            }
            const int r0 = (kk * 8 + c0) * 136;
            const int r1 = r0 + 4 * 136;
            uint32_t ah[4][4], al[4][4], bh[8][2], bl[8][2];
#pragma unroll
            for (int mf = 0; mf < 4; ++mf) {
                const int col = wm + mf * 16 + g;
                ah[mf][0] = AsH[r0 + col];
                ah[mf][1] = AsH[r0 + col + 8];
                ah[mf][2] = AsH[r1 + col];
                ah[mf][3] = AsH[r1 + col + 8];
                al[mf][0] = AsL[r0 + col];
                al[mf][1] = AsL[r0 + col + 8];
                al[mf][2] = AsL[r1 + col];
                al[mf][3] = AsL[r1 + col + 8];
            }
#pragma unroll
            for (int nf = 0; nf < 8; ++nf) {
                const int q0 = r0 + wn + nf * 8 + g;
                const int q1 = q0 + 4 * 136;
                bh[nf][0] = BsH[q0];
                bh[nf][1] = BsH[q1];
                bl[nf][0] = BsL[q0];
                bl[nf][1] = BsL[q1];
            }
            // pass-separated sweeps: consecutive MMAs hit different accumulators
#pragma unroll
            for (int mf = 0; mf < 4; ++mf)
#pragma unroll
                for (int nf = 0; nf < 8; ++nf)
                    mma16(acc[mf][nf], ah[mf], bh[nf]);
#pragma unroll
            for (int mf = 0; mf < 4; ++mf)
#pragma unroll
                for (int nf = 0; nf < 8; ++nf)
                    mma16(acc[mf][nf], ah[mf], bl[nf]);
#pragma unroll
            for (int mf = 0; mf < 4; ++mf)
#pragma unroll
                for (int nf = 0; nf < 8; ++nf)
                    mma16(acc[mf][nf], al[mf], bh[nf]);
        }
        CP_COMMIT();
        stc = (stc == 2) ? 0 : stc + 1;
        stf = (stf == 2) ? 0 : stf + 1;
    }

    // ---------------- epilogue: bias, NHWC store (coalesced), fused stats ----------------
    float s1[16], s2[16];
#pragma unroll
    for (int i = 0; i < 16; ++i) { s1[i] = 0.f; s2[i] = 0.f; }

#pragma unroll
    for (int mf = 0; mf < 4; ++mf) {
#pragma unroll
        for (int rr = 0; rr < 2; ++rr) {
            const int m = mt + wm + mf * 16 + g + rr * 8;
            float* orow = g_bufA + (size_t)m * CH;
#pragma unroll
            for (int nf = 0; nf < 8; ++nf) {
                const int c = nt + wn + nf * 8 + c0 * 2;
                const float v0 = acc[mf][nf][rr * 2]     + __ldg(&bias[c]);
                const float v1 = acc[mf][nf][rr * 2 + 1] + __ldg(&bias[c + 1]);
                *(float2*)(orow + c) = make_float2(v0, v1);
                s1[nf * 2]     += v0; s2[nf * 2]     += v0 * v0;
                s1[nf * 2 + 1] += v1; s2[nf * 2 + 1] += v1 * v1;
            }
        }
    }
    __syncthreads();
#pragma unroll
    for (int nf = 0; nf < 8; ++nf) {
        const int cl = wn + nf * 8 + c0 * 2;
        atomicAdd(&sRed1[cl],     s1[nf * 2]);
        atomicAdd(&sRed2[cl],     s2[nf * 2]);
        atomicAdd(&sRed1[cl + 1], s1[nf * 2 + 1]);
        atomicAdd(&sRed2[cl + 1], s2[nf * 2 + 1]);
    }
    __syncthreads();
    atomicAdd(&g_sum[nt + tid], sRed1[tid]);
    atomicAdd(&g_sq [nt + tid], sRed2[tid]);
}

// ---------------- BN+ReLU+split via 32x32 smem transpose: NHWC -> [ci2][M] ----------------
__global__ void k_bnsplit_t(const float* __restrict__ gm,
                            const float* __restrict__ bt)
{
    __shared__ float s[32][33];
    __shared__ float ssc[32], ssh[32];
    const int cb = blockIdx.x;
    const int n  = blockIdx.y;
    const int pb = blockIdx.z;
    const int tx = threadIdx.x, ty = threadIdx.y;
    const int tid = ty * 32 + tx;
    const float invN = 1.0f / (float)MTOT;

    if (tid < 32) {
        const int c = cb * 32 + tid;
        float m = g_sum[c] * invN;
        float v = g_sq[c] * invN - m * m;
        float sc = rsqrtf(v + EPS_BN) * __ldg(&gm[c]);
        ssc[tid] = sc;
        ssh[tid] = __ldg(&bt[c]) - m * sc;
    }
    __syncthreads();

    const int p0 = pb * 32;
#pragma unroll
    for (int yy = 0; yy < 4; ++yy) {
        const int p = p0 + ty + yy * 8;
        float x = (p < HWSZ)
                ? g_bufA[((size_t)n * HWSZ + p) * CH + cb * 32 + tx] : 0.f;
        s[tx][ty + yy * 8] = fmaxf(fmaf(x, ssc[tx], ssh[tx]), 0.f);
    }
    __syncthreads();
#pragma unroll
    for (int yy = 0; yy < 2; ++yy) {
        const int ci2l = ty + yy * 8;       // 0..15
        const int p = p0 + tx;
        if (p < HWSZ) {
            float y0 = s[2 * ci2l][tx];
            float y1 = s[2 * ci2l + 1][tx];
            uint16_t h0, l0, h1, l1;
            bfsplit(y0, h0, l0);
            bfsplit(y1, h1, l1);
            const size_t i = (size_t)(cb * 16 + ci2l) * MTOT + (size_t)n * HWSZ + p;
            g_aH[i] = ((uint32_t)h1 << 16) | h0;
            g_aL[i] = ((uint32_t)l1 << 16) | l0;
        }
    }
}

// ---------------- fused final BN + ReLU + cumtrapz along w ----------------
// grid NIMG*HH, block 256 (c). Reads bufA NHWC, writes g_ft + g_Ux.
__global__ void k_bn_cumx(const float* __restrict__ gm,
                          const float* __restrict__ bt)
{
    const int nh = blockIdx.x;
    const int c  = threadIdx.x;
    const float invN = 1.0f / (float)MTOT;
    float m  = g_sum[c] * invN;
    float v  = g_sq[c] * invN - m * m;
    float sc = rsqrtf(v + EPS_BN) * __ldg(&gm[c]);
    float sh = __ldg(&bt[c]) - m * sc;

    size_t base = ((size_t)nh * WW) * CH + c;
    float prev = fmaxf(fmaf(g_bufA[base], sc, sh), 0.f);
    g_ft[base] = prev;
    g_Ux[base] = 0.f;
    float u = 0.f;
    for (int w = 1; w < WW; ++w) {
        float f = fmaxf(fmaf(g_bufA[base + (size_t)w * CH], sc, sh), 0.f);
        u += 0.5f * (prev + f);
        g_ft[base + (size_t)w * CH] = f;
        g_Ux[base + (size_t)w * CH] = u;
        prev = f;
    }
}

// ---------------- cumtrapz along h ----------------
__global__ void k_cumy()
{
    const int nw = blockIdx.x;
    const int n  = nw / WW;
    const int w  = nw - n * WW;
    const int c  = threadIdx.x;
    size_t base   = ((size_t)n * HWSZ + w) * CH + c;
    size_t stride = (size_t)WW * CH;
    float pf = g_ft[base], pu = g_Ux[base];
    float uy = 0.f, tt = 0.f;
    g_Uy[base] = 0.f;
    g_T[base]  = 0.f;
    for (int hh = 1; hh < HH; ++hh) {
        float f = g_ft[base + hh * stride];
        float u = g_Ux[base + hh * stride];
        uy += 0.5f * (pf + f);
        tt += 0.5f * (pu + u);
        g_Uy[base + hh * stride] = uy;
        g_T [base + hh * stride] = tt;
        pf = f; pu = u;
    }
}

// ---------------- PrRoI pooling (+ FC-stat zeroing) ----------------
__global__ void k_pool(const float* __restrict__ props)
{
    const int p = blockIdx.x;
    const int c = threadIdx.x;
    if (p == 0) { g_fsum[c] = 0.f; g_fsq[c] = 0.f; }
    const float px = __ldg(&props[p * 4 + 0]);
    const float py = __ldg(&props[p * 4 + 1]);
    const float pw = __ldg(&props[p * 4 + 2]);
    const float ph = __ldg(&props[p * 4 + 3]);
    const float x1 = px * 20.f;
    const float y1 = py * 20.f;
    const float x2 = (px + pw) * 20.f;
    const float y2 = (py + ph) * 20.f;
    const float bw = (x2 - x1) * 0.25f;
    const float bh = (y2 - y1) * 0.25f;

    int   wx[5], hy[5];
    float px0[5], px1[5], py0[5], py1[5];
#pragma unroll
    for (int i = 0; i < 5; ++i) {
        float xs = fminf(fmaxf(x1 + bw * (float)i, 0.f), 35.f);
        int w0 = min((int)floorf(xs), 34);
        float sx = xs - (float)w0;
        float q = 0.5f * sx * sx;
        px1[i] = q; px0[i] = sx - q; wx[i] = w0;

        float ys = fminf(fmaxf(y1 + bh * (float)i, 0.f), 35.f);
        int h0 = min((int)floorf(ys), 34);
        float sy = ys - (float)h0;
        float r = 0.5f * sy * sy;
        py1[i] = r; py0[i] = sy - r; hy[i] = h0;
    }

    const int b = p >> 4;
    float G[5][5];
#pragma unroll
    for (int iy = 0; iy < 5; ++iy) {
#pragma unroll
        for (int ix = 0; ix < 5; ++ix) {
            size_t i00 = (((size_t)b * HH + hy[iy]) * WW + wx[ix]) * CH + c;
            size_t i01 = i00 + CH;
            size_t i10 = i00 + (size_t)WW * CH;
            size_t i11 = i10 + CH;
            G[iy][ix] = g_T[i00]
                      + g_Uy[i00] * px0[ix] + g_Uy[i01] * px1[ix]
                      + py0[iy] * (g_Ux[i00] + g_ft[i00] * px0[ix] + g_ft[i01] * px1[ix])
                      + py1[iy] * (g_Ux[i10] + g_ft[i10] * px0[ix] + g_ft[i11] * px1[ix]);
        }
    }
    const float area = bw * bh;
    const float inv  = (area > 1e-8f) ? (1.f / fmaxf(area, 1e-8f)) : 0.f;
    float* out = g_rf + (size_t)p * FCK + c * 16;
#pragma unroll
    for (int iy = 0; iy < 4; ++iy)
#pragma unroll
        for (int ix = 0; ix < 4; ++ix)
            out[iy * 4 + ix] =
                (G[iy + 1][ix + 1] - G[iy][ix + 1] - G[iy + 1][ix] + G[iy][ix]) * inv;
}

// ---------------- FC GEMM + fused stats ----------------
__global__ void __launch_bounds__(256) k_fc(const float* __restrict__ Wfc,
                                            const float* __restrict__ bias)
{
    __shared__ float As[16][65];
    __shared__ float Bs[16][65];
    __shared__ float sRed[128];

    const int tid = threadIdx.x;
    const int mt  = blockIdx.x * 64;
    const int nt  = blockIdx.y * 64;
    const int lr  = tid >> 2;
    const int lk  = (tid & 3) * 4;
    const int tm  = tid & 15;
    const int tn  = tid >> 4;

    float acc[4][4];
#pragma unroll
    for (int i = 0; i < 4; ++i)
#pragma unroll
        for (int j = 0; j < 4; ++j) acc[i][j] = 0.f;

    for (int kc = 0; kc < FCK / 16; ++kc) {
        float4 av = *(const float4*)&g_rf[(size_t)(mt + lr) * FCK + kc * 16 + lk];
        float4 bv = *(const float4*)&Wfc [(size_t)(nt + lr) * FCK + kc * 16 + lk];
        __syncthreads();
        As[lk + 0][lr] = av.x; As[lk + 1][lr] = av.y;
        As[lk + 2][lr] = av.z; As[lk + 3][lr] = av.w;
        Bs[lk + 0][lr] = bv.x; Bs[lk + 1][lr] = bv.y;
        Bs[lk + 2][lr] = bv.z; Bs[lk + 3][lr] = bv.w;
        __syncthreads();
#pragma unroll
        for (int kk = 0; kk < 16; ++kk) {
            float a[4], b[4];
#pragma unroll
            for (int i = 0; i < 4; ++i) a[i] = As[kk][tm + 16 * i];
#pragma unroll
            for (int j = 0; j < 4; ++j) b[j] = Bs[kk][tn * 4 + j];
#pragma unroll
            for (int i = 0; i < 4; ++i)
#pragma unroll
                for (int j = 0; j < 4; ++j)
                    acc[i][j] = fmaf(a[i], b[j], acc[i][j]);
        }
    }

    float s1a[4], s2a[4];
#pragma unroll
    for (int j = 0; j < 4; ++j) {
        const int c = nt + tn * 4 + j;
        const float bv = __ldg(&bias[c]);
        float s1 = 0.f, s2 = 0.f;
#pragma unroll
        for (int i = 0; i < 4; ++i) {
            const int m = mt + tm + 16 * i;
            float v = acc[i][j] + bv;
            g_fc[(size_t)m * CH + c] = v;
            s1 += v;
            s2 += v * v;
        }
        s1a[j] = s1; s2a[j] = s2;
    }
    __syncthreads();
    if (tid < 128) sRed[tid] = 0.f;
    __syncthreads();
#pragma unroll
    for (int j = 0; j < 4; ++j) {
        const int cl = tn * 4 + j;
        atomicAdd(&sRed[cl], s1a[j]);
        atomicAdd(&sRed[64 + cl], s2a[j]);
    }
    __syncthreads();
    if (tid < 64) {
        atomicAdd(&g_fsum[nt + tid], sRed[tid]);
        atomicAdd(&g_fsq [nt + tid], sRed[64 + tid]);
    }
}

// ---------------- FC BN + ReLU + IoU head ----------------
__global__ void k_fcbn_iou(const float* __restrict__ gm,
                           const float* __restrict__ bt,
                           const float* __restrict__ iw,
                           const float* __restrict__ ib,
                           float* __restrict__ out)
{
    __shared__ float sred[8];
    const int p = blockIdx.x;
    const int c = threadIdx.x;
    const float invN = 1.f / (float)NROI;
    float m  = g_fsum[c] * invN;
    float v  = g_fsq[c] * invN - m * m;
    float sc = rsqrtf(v + EPS_BN) * __ldg(&gm[c]);
    float sh = __ldg(&bt[c]) - m * sc;
    float x  = fmaxf(fmaf(g_fc[(size_t)p * CH + c], sc, sh), 0.f);
    float t  = x * __ldg(&iw[c]);
#pragma unroll
    for (int o = 16; o; o >>= 1) t += __shfl_xor_sync(0xffffffffu, t, o);
    if ((c & 31) == 0) sred[c >> 5] = t;
    __syncthreads();
    if (c == 0) {
        float s = 0.f;
#pragma unroll
        for (int i = 0; i < 8; ++i) s += sred[i];
        out[p] = s + __ldg(&ib[0]);
    }
}

// ---------------- launch sequence ----------------
extern "C" void kernel_launch(void* const* d_in, const int* in_sizes, int n_in,
                              void* d_out, int out_size)
{
    const float* feat  = (const float*)d_in[0];
    const float* props = (const float*)d_in[1];
    const float* c1w = (const float*)d_in[2];
    const float* c1b = (const float*)d_in[3];
    const float* b1g = (const float*)d_in[4];
    const float* b1b = (const float*)d_in[5];
    const float* c2w = (const float*)d_in[6];
    const float* c2b = (const float*)d_in[7];
    const float* b2g = (const float*)d_in[8];
    const float* b2b = (const float*)d_in[9];
    const float* c3w = (const float*)d_in[10];
    const float* c3b = (const float*)d_in[11];
    const float* b3g = (const float*)d_in[12];
    const float* b3b = (const float*)d_in[13];
    const float* fcw = (const float*)d_in[14];
    const float* fcb = (const float*)d_in[15];
    const float* fbg = (const float*)d_in[16];
    const float* fbb = (const float*)d_in[17];
    const float* iw  = (const float*)d_in[18];
    const float* ib  = (const float*)d_in[19];
    float* out = (float*)d_out;

    const int CONV_SMEM = 3 * STG_B;   // 104448 B per CTA, 2 CTAs/SM
    cudaFuncSetAttribute(k_conv_m, cudaFuncAttributeMaxDynamicSharedMemorySize, CONV_SMEM);

    const dim3 convGrid(MTOT / 128, 2);
    const int  wpBlocks = NK2;                  // 1152
    const int  spBlocks = 128 * MTOT / 256;     // 20736 (cvtA)

    // conv1  (k_wprep zeroes conv stats in block 0)
    k_wprep<<<wpBlocks, 256>>>(c1w);
    k_cvtA<<<spBlocks, 256>>>(feat);
    k_conv_m<<<convGrid, 128, CONV_SMEM>>>(c1b);
    k_bnsplit_t<<<dim3(8, NIMG, 41), dim3(32, 8)>>>(b1g, b1b);
    // conv2
    k_wprep<<<wpBlocks, 256>>>(c2w);
    k_conv_m<<<convGrid, 128, CONV_SMEM>>>(c2b);
    k_bnsplit_t<<<dim3(8, NIMG, 41), dim3(32, 8)>>>(b2g, b2b);
    // conv3
    k_wprep<<<wpBlocks, 256>>>(c3w);
    k_conv_m<<<convGrid, 128, CONV_SMEM>>>(c3b);

    // fused final BN + cumx, then cumy (integral images, NHWC)
    k_bn_cumx<<<NIMG * HH, 256>>>(b3g, b3b);
    k_cumy<<<NIMG * WW, 256>>>();

    // PrRoI pooling (zeroes FC stats in block 0)
    k_pool<<<NROI, 256>>>(props);

    // FC + BN + IoU
    k_fc<<<dim3(NROI / 64, CH / 64), 256>>>(fcw, fcb);
    k_fcbn_iou<<<NROI, 256>>>(fbg, fbb, iw, ib, out);
}